// round 8
// baseline (speedup 1.0000x reference)
#include <cuda_runtime.h>
#include <cstdint>
#include <cstdio>

// ---------------------------------------------------------------------------
// Problem constants
// ---------------------------------------------------------------------------
#define TSTEPS 4096
#define NTT    4095      // T-1 rows
#define VDIM   88
#define HDIM   512
#define RDIM   512
#define GS     20

// ---------------------------------------------------------------------------
// Scratch (static device globals — no runtime allocation allowed)
// ---------------------------------------------------------------------------
__device__ float  g_a    [NTT * RDIM];   // wvu@v_t + bu
__device__ float  g_uprev[NTT * RDIM];   // u_prev[t]
__device__ float  g_bht  [NTT * HDIM];
__device__ float  g_bvt  [NTT * VDIM];
__device__ float  g_h    [NTT * HDIM];
__device__ float  g_v    [NTT * VDIM];
__device__ float  g_wT   [VDIM * HDIM];  // w transposed -> (V, H)
__device__ double g_ce   [256];
__device__ double g_n2uv [64];
__device__ double g_n2uh [64];

// ---------------------------------------------------------------------------
// Helpers
// ---------------------------------------------------------------------------
__device__ __forceinline__ uint32_t smem_u32(const void* p) {
    return (uint32_t)__cvta_generic_to_shared(p);
}
__device__ __forceinline__ void cluster_sync_() {
    asm volatile("barrier.cluster.arrive.aligned;\n\t"
                 "barrier.cluster.wait.aligned;" ::: "memory");
}

// ---------------------------------------------------------------------------
// Generic NT GEMM:  C[m][n] = sum_k A[m][k]*B[n][k] + bias[m*bias_stride + n]
// Optional Bernoulli epilogue: C = (sigmoid(val) > rnd[m*rnd_stride+n]) ? 1 : 0
// 64x64 tile, K-chunks of 16, 256 threads, 4x4 register tile per thread.
// ---------------------------------------------------------------------------
__global__ void __launch_bounds__(256) gemm_nt(
    const float* __restrict__ A, int lda,
    const float* __restrict__ B, int ldb,
    const float* __restrict__ bias, int bias_stride,
    const float* __restrict__ rnd, int rnd_stride,
    float* __restrict__ C, int ldc,
    int M, int N, int K)
{
    __shared__ float As[16][64];
    __shared__ float Bs[16][64];

    const int tid = threadIdx.x;
    const int tx = tid & 15, ty = tid >> 4;
    const int m0 = blockIdx.x * 64;
    const int n0 = blockIdx.y * 64;

    const int srow = tid >> 2;       // 0..63 (tile row loaded by this thread)
    const int kq   = (tid & 3) * 4;  // 0,4,8,12

    float acc[4][4] = {};

    for (int k0 = 0; k0 < K; k0 += 16) {
        // stage A tile (64 rows x 16 k), transposed into As[k][m]
        {
            const int m = m0 + srow;
            const bool mok = (m < M);
            const float* Ap = A + (size_t)m * lda + k0 + kq;
#pragma unroll
            for (int i = 0; i < 4; i++) {
                int k = k0 + kq + i;
                As[kq + i][srow] = (mok && k < K) ? Ap[i] : 0.f;
            }
            const int n = n0 + srow;
            const bool nok = (n < N);
            const float* Bp = B + (size_t)n * ldb + k0 + kq;
#pragma unroll
            for (int i = 0; i < 4; i++) {
                int k = k0 + kq + i;
                Bs[kq + i][srow] = (nok && k < K) ? Bp[i] : 0.f;
            }
        }
        __syncthreads();
#pragma unroll
        for (int k = 0; k < 16; k++) {
            float4 a4 = *(const float4*)&As[k][ty * 4];
            float4 b4 = *(const float4*)&Bs[k][tx * 4];
            float av[4] = {a4.x, a4.y, a4.z, a4.w};
            float bv[4] = {b4.x, b4.y, b4.z, b4.w};
#pragma unroll
            for (int r = 0; r < 4; r++)
#pragma unroll
                for (int c = 0; c < 4; c++)
                    acc[r][c] = fmaf(av[r], bv[c], acc[r][c]);
        }
        __syncthreads();
    }

#pragma unroll
    for (int r = 0; r < 4; r++) {
        const int m = m0 + ty * 4 + r;
        if (m >= M) continue;
#pragma unroll
        for (int c = 0; c < 4; c++) {
            const int n = n0 + tx * 4 + c;
            if (n >= N) continue;
            float val = acc[r][c] + bias[(size_t)m * bias_stride + n];
            if (rnd) {
                float s = 1.f / (1.f + expf(-val));
                val = (s > rnd[(size_t)m * rnd_stride + n]) ? 1.f : 0.f;
            }
            C[(size_t)m * ldc + n] = val;
        }
    }
}

// ---------------------------------------------------------------------------
// Sequential u recurrence: cluster of 8 CTAs, wuu resident in registers.
// CTA c owns outputs [c*64, c*64+64). Warp w owns 4 outputs, lanes split K.
// Per step: partial dots -> butterfly all-reduce -> tanh -> DSMEM broadcast
// of each CTA's 64 new u values to all 8 CTAs -> cluster barrier.
// ---------------------------------------------------------------------------
__global__ void __cluster_dims__(8, 1, 1) __launch_bounds__(512, 1)
recur_kernel(const float* __restrict__ wuu, const float* __restrict__ a,
             const float* __restrict__ u0, float* __restrict__ uprev)
{
    __shared__ float u_s[2][RDIM];

    unsigned rank;
    asm("mov.u32 %0, %%cluster_ctarank;" : "=r"(rank));

    const int tid = threadIdx.x;
    const int w = tid >> 5, l = tid & 31;
    const int obase = (int)rank * 64 + w * 4;

    // Preload this thread's 4x16 slice of wuu into registers (coalesced).
    float wreg[64];
#pragma unroll
    for (int oo = 0; oo < 4; oo++)
#pragma unroll
        for (int j = 0; j < 16; j++)
            wreg[oo * 16 + j] = wuu[(obase + oo) * RDIM + l + 32 * j];

    u_s[0][tid] = u0[tid];
    if (rank == 0) uprev[tid] = u0[tid];

    const uint32_t base0 = smem_u32(&u_s[0][0]);
    const uint32_t base1 = smem_u32(&u_s[1][0]);

    cluster_sync_();

    int p = 0;
    for (int t = 0; t < NTT - 1; t++) {
        // prefetch bias term early (hides L2 latency behind the FMA chain)
        float av = 0.f;
        if (l < 4) av = a[t * RDIM + obase + l];

        const float* us = u_s[p];
        float a0 = 0.f, a1 = 0.f, a2 = 0.f, a3 = 0.f;
#pragma unroll
        for (int j = 0; j < 16; j++) {
            float uv = us[l + 32 * j];
            a0 = fmaf(wreg[j],      uv, a0);
            a1 = fmaf(wreg[16 + j], uv, a1);
            a2 = fmaf(wreg[32 + j], uv, a2);
            a3 = fmaf(wreg[48 + j], uv, a3);
        }
#pragma unroll
        for (int off = 16; off; off >>= 1) {
            a0 += __shfl_xor_sync(0xffffffffu, a0, off);
            a1 += __shfl_xor_sync(0xffffffffu, a1, off);
            a2 += __shfl_xor_sync(0xffffffffu, a2, off);
            a3 += __shfl_xor_sync(0xffffffffu, a3, off);
        }
        if (l < 4) {
            float acc = (l == 0) ? a0 : (l == 1) ? a1 : (l == 2) ? a2 : a3;
            float un = tanhf(acc + av);
            uint32_t dst = (p ? base0 : base1) + 4u * (uint32_t)(obase + l);
#pragma unroll
            for (unsigned r = 0; r < 8; r++) {
                uint32_t rem;
                asm volatile("mapa.shared::cluster.u32 %0, %1, %2;"
                             : "=r"(rem) : "r"(dst), "r"(r));
                asm volatile("st.shared::cluster.f32 [%0], %1;"
                             :: "r"(rem), "f"(un) : "memory");
            }
            uprev[(t + 1) * RDIM + obase + l] = un;
        }
        cluster_sync_();   // arrive=release orders the DSMEM stores
        p ^= 1;
    }
}

// ---------------------------------------------------------------------------
// Small utility kernels
// ---------------------------------------------------------------------------
__global__ void transpose_w_kernel(const float* __restrict__ w, float* __restrict__ wT) {
    int idx = blockIdx.x * blockDim.x + threadIdx.x;
    if (idx < HDIM * VDIM) {
        int i = idx / VDIM, j = idx % VDIM;
        wT[j * HDIM + i] = w[idx];
    }
}

__global__ void ce_partial_kernel(const float* __restrict__ visible,
                                  const float* __restrict__ bvt, double* __restrict__ out) {
    __shared__ double sd[256];
    double s = 0.0;
    const int n = NTT * VDIM;
    for (int idx = blockIdx.x * 256 + threadIdx.x; idx < n; idx += gridDim.x * 256) {
        float x = bvt[idx];
        float y = 1.f / (1.f + expf(-x));
        float v = visible[idx + VDIM];  // visible[(t+1)*V + j] == visible[idx + V]
        float term = -(v * logf(1e-6f + y) + (1.f - v) * logf(1e-6f + 1.f - y));
        s += (double)term;
    }
    sd[threadIdx.x] = s;
    __syncthreads();
    for (int o = 128; o; o >>= 1) {
        if (threadIdx.x < o) sd[threadIdx.x] += sd[threadIdx.x + o];
        __syncthreads();
    }
    if (threadIdx.x == 0) out[blockIdx.x] = sd[0];
}

__global__ void sqsum_kernel(const float* __restrict__ x, int n, double* __restrict__ out) {
    __shared__ double sd[256];
    double s = 0.0;
    for (int i = blockIdx.x * 256 + threadIdx.x; i < n; i += gridDim.x * 256) {
        float f = x[i];
        s += (double)f * (double)f;
    }
    sd[threadIdx.x] = s;
    __syncthreads();
    for (int o = 128; o; o >>= 1) {
        if (threadIdx.x < o) sd[threadIdx.x] += sd[threadIdx.x + o];
        __syncthreads();
    }
    if (threadIdx.x == 0) out[blockIdx.x] = sd[0];
}

__global__ void mse_kernel(const float* __restrict__ visible,
                           const float* __restrict__ vneg, float* __restrict__ out) {
    int t = blockIdx.x * blockDim.x + threadIdx.x;
    if (t < NTT) {
        float s = 0.f;
#pragma unroll 8
        for (int j = 0; j < VDIM; j++)
            s += fabsf(visible[(t + 1) * VDIM + j] - vneg[t * VDIM + j]);
        out[1 + t] = s / 88.0f;
    }
}

__global__ void finalize_kernel(const double* __restrict__ ce,
                                const double* __restrict__ n2uv,
                                const double* __restrict__ n2uh,
                                float* __restrict__ out) {
    __shared__ double s[256];
    const int t = threadIdx.x;
    s[t] = ce[t];
    __syncthreads();
    for (int o = 128; o; o >>= 1) { if (t < o) s[t] += s[t + o]; __syncthreads(); }
    double ce_sum = s[0];
    __syncthreads();
    s[t] = (t < 64) ? n2uv[t] : 0.0;
    __syncthreads();
    for (int o = 128; o; o >>= 1) { if (t < o) s[t] += s[t + o]; __syncthreads(); }
    double suv = s[0];
    __syncthreads();
    s[t] = (t < 64) ? n2uh[t] : 0.0;
    __syncthreads();
    for (int o = 128; o; o >>= 1) { if (t < o) s[t] += s[t + o]; __syncthreads(); }
    double suh = s[0];
    if (t == 0) {
        double reg = 0.2 * (sqrt(suv) + sqrt(suh));
        out[0]      = (float)(ce_sum / (double)TSTEPS + reg);
        out[TSTEPS] = (float)reg;   // index 4096
    }
}

// ---------------------------------------------------------------------------
// Launch
// ---------------------------------------------------------------------------
extern "C" void kernel_launch(void* const* d_in, const int* in_sizes, int n_in,
                              void* d_out, int out_size) {
    const float* visible = (const float*)d_in[0];
    const float* rand_h  = (const float*)d_in[1];
    const float* rand_v  = (const float*)d_in[2];
    const float* w       = (const float*)d_in[3];
    const float* wuu     = (const float*)d_in[4];
    const float* wuv     = (const float*)d_in[5];
    const float* wuh     = (const float*)d_in[6];
    const float* wvu     = (const float*)d_in[7];
    const float* bv      = (const float*)d_in[8];
    const float* bh      = (const float*)d_in[9];
    const float* bu      = (const float*)d_in[10];
    const float* u0      = (const float*)d_in[11];
    float* out = (float*)d_out;

    void *pa, *pu, *pbh, *pbv, *ph, *pv, *pwT, *pce, *pnuv, *pnuh;
    cudaGetSymbolAddress(&pa,   g_a);
    cudaGetSymbolAddress(&pu,   g_uprev);
    cudaGetSymbolAddress(&pbh,  g_bht);
    cudaGetSymbolAddress(&pbv,  g_bvt);
    cudaGetSymbolAddress(&ph,   g_h);
    cudaGetSymbolAddress(&pv,   g_v);
    cudaGetSymbolAddress(&pwT,  g_wT);
    cudaGetSymbolAddress(&pce,  g_ce);
    cudaGetSymbolAddress(&pnuv, g_n2uv);
    cudaGetSymbolAddress(&pnuh, g_n2uh);

    // 0) transpose w -> wT (V, H)
    transpose_w_kernel<<<(HDIM * VDIM + 255) / 256, 256>>>(w, (float*)pwT);

    // 1) a[t] = v_seq[t] @ wvu^T + bu   (M=4095, N=512, K=88); v_seq = visible+V
    {
        dim3 g((NTT + 63) / 64, (RDIM + 63) / 64);
        gemm_nt<<<g, 256>>>(visible + VDIM, VDIM, wvu, VDIM,
                            bu, 0, nullptr, 0,
                            (float*)pa, RDIM, NTT, RDIM, VDIM);
    }

    // 2) sequential recurrence -> u_prev
    recur_kernel<<<8, 512>>>(wuu, (const float*)pa, u0, (float*)pu);

    // 3) bh_t = u_prev @ wuh^T + bh ; bv_t = u_prev @ wuv^T + bv
    {
        dim3 g((NTT + 63) / 64, (HDIM + 63) / 64);
        gemm_nt<<<g, 256>>>((const float*)pu, RDIM, wuh, RDIM,
                            bh, 0, nullptr, 0,
                            (float*)pbh, HDIM, NTT, HDIM, RDIM);
        dim3 g2((NTT + 63) / 64, (VDIM + 63) / 64);
        gemm_nt<<<g2, 256>>>((const float*)pu, RDIM, wuv, RDIM,
                             bv, 0, nullptr, 0,
                             (float*)pbv, VDIM, NTT, VDIM, RDIM);
    }

    // 4) Gibbs: v starts as v_seq
    cudaMemcpyAsync(pv, visible + VDIM, (size_t)NTT * VDIM * sizeof(float),
                    cudaMemcpyDeviceToDevice, 0);
    {
        dim3 gh((NTT + 63) / 64, (HDIM + 63) / 64);
        dim3 gv((NTT + 63) / 64, (VDIM + 63) / 64);
        for (int s = 0; s < GS; s++) {
            // h = 1[ sigmoid(v @ w^T + bh_t) > rand_h[:,s,:] ]
            gemm_nt<<<gh, 256>>>((const float*)pv, VDIM, w, VDIM,
                                 (const float*)pbh, HDIM,
                                 rand_h + (size_t)s * HDIM, GS * HDIM,
                                 (float*)ph, HDIM, NTT, HDIM, VDIM);
            // v = 1[ sigmoid(h @ w + bv_t) > rand_v[:,s,:] ]   (B = wT, NT form)
            gemm_nt<<<gv, 256>>>((const float*)ph, HDIM, (const float*)pwT, HDIM,
                                 (const float*)pbv, VDIM,
                                 rand_v + (size_t)s * VDIM, GS * VDIM,
                                 (float*)pv, VDIM, NTT, VDIM, HDIM);
        }
    }

    // 5) reductions
    ce_partial_kernel<<<256, 256>>>(visible, (const float*)pbv, (double*)pce);
    sqsum_kernel<<<64, 256>>>(wuv, VDIM * RDIM, (double*)pnuv);
    sqsum_kernel<<<64, 256>>>(wuh, HDIM * RDIM, (double*)pnuh);
    mse_kernel<<<(NTT + 255) / 256, 256>>>(visible, (const float*)pv, out);
    finalize_kernel<<<1, 256>>>((const double*)pce, (const double*)pnuv,
                                (const double*)pnuh, out);
}

// round 9
// speedup vs baseline: 1.5723x; 1.5723x over previous
#include <cuda_runtime.h>
#include <cstdint>
#include <cstdio>

// ---------------------------------------------------------------------------
// Problem constants
// ---------------------------------------------------------------------------
#define TSTEPS 4096
#define NTT    4095      // T-1 rows
#define VDIM   88
#define HDIM   512
#define RDIM   512
#define GS     20

// ---------------------------------------------------------------------------
// Scratch (static device globals — no runtime allocation allowed)
// ---------------------------------------------------------------------------
__device__ float  g_a    [NTT * RDIM];   // wvu@v_t + bu
__device__ float  g_uprev[NTT * RDIM];   // u_prev[t]
__device__ float  g_bht  [NTT * HDIM];
__device__ float  g_bvt  [NTT * VDIM];
__device__ float  g_h    [NTT * HDIM];
__device__ float  g_v    [NTT * VDIM];
__device__ float  g_wT   [VDIM * HDIM];  // w transposed -> (V, H)
__device__ double g_ce   [256];
__device__ double g_n2uv [64];
__device__ double g_n2uh [64];

// ---------------------------------------------------------------------------
// Helpers
// ---------------------------------------------------------------------------
__device__ __forceinline__ uint32_t smem_u32(const void* p) {
    return (uint32_t)__cvta_generic_to_shared(p);
}
__device__ __forceinline__ void cluster_sync_() {
    asm volatile("barrier.cluster.arrive.aligned;\n\t"
                 "barrier.cluster.wait.aligned;" ::: "memory");
}

// ---------------------------------------------------------------------------
// Generic NT GEMM:  C[m][n] = sum_k A[m][k]*B[n][k] + bias[m*bias_stride + n]
// Optional Bernoulli epilogue: C = (sigmoid(val) > rnd[m*rnd_stride+n]) ? 1 : 0
// 64x64 tile, K-chunks of 16, 256 threads, 4x4 register tile per thread.
// ---------------------------------------------------------------------------
__global__ void __launch_bounds__(256) gemm_nt(
    const float* __restrict__ A, int lda,
    const float* __restrict__ B, int ldb,
    const float* __restrict__ bias, int bias_stride,
    const float* __restrict__ rnd, int rnd_stride,
    float* __restrict__ C, int ldc,
    int M, int N, int K)
{
    __shared__ float As[16][64];
    __shared__ float Bs[16][64];

    const int tid = threadIdx.x;
    const int tx = tid & 15, ty = tid >> 4;
    const int m0 = blockIdx.x * 64;
    const int n0 = blockIdx.y * 64;

    const int srow = tid >> 2;       // 0..63 (tile row loaded by this thread)
    const int kq   = (tid & 3) * 4;  // 0,4,8,12

    float acc[4][4] = {};

    for (int k0 = 0; k0 < K; k0 += 16) {
        // stage A tile (64 rows x 16 k), transposed into As[k][m]
        {
            const int m = m0 + srow;
            const bool mok = (m < M);
            const float* Ap = A + (size_t)m * lda + k0 + kq;
#pragma unroll
            for (int i = 0; i < 4; i++) {
                int k = k0 + kq + i;
                As[kq + i][srow] = (mok && k < K) ? Ap[i] : 0.f;
            }
            const int n = n0 + srow;
            const bool nok = (n < N);
            const float* Bp = B + (size_t)n * ldb + k0 + kq;
#pragma unroll
            for (int i = 0; i < 4; i++) {
                int k = k0 + kq + i;
                Bs[kq + i][srow] = (nok && k < K) ? Bp[i] : 0.f;
            }
        }
        __syncthreads();
#pragma unroll
        for (int k = 0; k < 16; k++) {
            float4 a4 = *(const float4*)&As[k][ty * 4];
            float4 b4 = *(const float4*)&Bs[k][tx * 4];
            float av[4] = {a4.x, a4.y, a4.z, a4.w};
            float bv[4] = {b4.x, b4.y, b4.z, b4.w};
#pragma unroll
            for (int r = 0; r < 4; r++)
#pragma unroll
                for (int c = 0; c < 4; c++)
                    acc[r][c] = fmaf(av[r], bv[c], acc[r][c]);
        }
        __syncthreads();
    }

#pragma unroll
    for (int r = 0; r < 4; r++) {
        const int m = m0 + ty * 4 + r;
        if (m >= M) continue;
#pragma unroll
        for (int c = 0; c < 4; c++) {
            const int n = n0 + tx * 4 + c;
            if (n >= N) continue;
            float val = acc[r][c] + bias[(size_t)m * bias_stride + n];
            if (rnd) {
                float s = 1.f / (1.f + expf(-val));
                val = (s > rnd[(size_t)m * rnd_stride + n]) ? 1.f : 0.f;
            }
            C[(size_t)m * ldc + n] = val;
        }
    }
}

// ---------------------------------------------------------------------------
// Sequential u recurrence: cluster of 8 CTAs, wuu resident in registers.
// CTA c owns outputs [c*64, c*64+64). Warp w owns 4 outputs, lanes split K.
// Per step: partial dots -> butterfly all-reduce -> tanh -> DSMEM broadcast
// of each CTA's 64 new u values to all 8 CTAs -> cluster barrier.
// ---------------------------------------------------------------------------
__global__ void __cluster_dims__(8, 1, 1) __launch_bounds__(512, 1)
recur_kernel(const float* __restrict__ wuu, const float* __restrict__ a,
             const float* __restrict__ u0, float* __restrict__ uprev)
{
    __shared__ float u_s[2][RDIM];

    unsigned rank;
    asm("mov.u32 %0, %%cluster_ctarank;" : "=r"(rank));

    const int tid = threadIdx.x;
    const int w = tid >> 5, l = tid & 31;
    const int obase = (int)rank * 64 + w * 4;

    // Preload this thread's 4x16 slice of wuu into registers (coalesced).
    float wreg[64];
#pragma unroll
    for (int oo = 0; oo < 4; oo++)
#pragma unroll
        for (int j = 0; j < 16; j++)
            wreg[oo * 16 + j] = wuu[(obase + oo) * RDIM + l + 32 * j];

    u_s[0][tid] = u0[tid];
    if (rank == 0) uprev[tid] = u0[tid];

    const uint32_t base0 = smem_u32(&u_s[0][0]);
    const uint32_t base1 = smem_u32(&u_s[1][0]);

    cluster_sync_();

    int p = 0;
    for (int t = 0; t < NTT - 1; t++) {
        // prefetch bias term early (hides L2 latency behind the FMA chain)
        float av = 0.f;
        if (l < 4) av = a[t * RDIM + obase + l];

        const float* us = u_s[p];
        float a0 = 0.f, a1 = 0.f, a2 = 0.f, a3 = 0.f;
#pragma unroll
        for (int j = 0; j < 16; j++) {
            float uv = us[l + 32 * j];
            a0 = fmaf(wreg[j],      uv, a0);
            a1 = fmaf(wreg[16 + j], uv, a1);
            a2 = fmaf(wreg[32 + j], uv, a2);
            a3 = fmaf(wreg[48 + j], uv, a3);
        }
#pragma unroll
        for (int off = 16; off; off >>= 1) {
            a0 += __shfl_xor_sync(0xffffffffu, a0, off);
            a1 += __shfl_xor_sync(0xffffffffu, a1, off);
            a2 += __shfl_xor_sync(0xffffffffu, a2, off);
            a3 += __shfl_xor_sync(0xffffffffu, a3, off);
        }
        if (l < 4) {
            float acc = (l == 0) ? a0 : (l == 1) ? a1 : (l == 2) ? a2 : a3;
            float un = tanhf(acc + av);
            uint32_t dst = (p ? base0 : base1) + 4u * (uint32_t)(obase + l);
#pragma unroll
            for (unsigned r = 0; r < 8; r++) {
                uint32_t rem;
                asm volatile("mapa.shared::cluster.u32 %0, %1, %2;"
                             : "=r"(rem) : "r"(dst), "r"(r));
                asm volatile("st.shared::cluster.f32 [%0], %1;"
                             :: "r"(rem), "f"(un) : "memory");
            }
            uprev[(t + 1) * RDIM + obase + l] = un;
        }
        cluster_sync_();   // arrive=release orders the DSMEM stores
        p ^= 1;
    }
}

// ---------------------------------------------------------------------------
// Small utility kernels
// ---------------------------------------------------------------------------
__global__ void transpose_w_kernel(const float* __restrict__ w, float* __restrict__ wT) {
    int idx = blockIdx.x * blockDim.x + threadIdx.x;
    if (idx < HDIM * VDIM) {
        int i = idx / VDIM, j = idx % VDIM;
        wT[j * HDIM + i] = w[idx];
    }
}

__global__ void ce_partial_kernel(const float* __restrict__ visible,
                                  const float* __restrict__ bvt, double* __restrict__ out) {
    __shared__ double sd[256];
    double s = 0.0;
    const int n = NTT * VDIM;
    for (int idx = blockIdx.x * 256 + threadIdx.x; idx < n; idx += gridDim.x * 256) {
        float x = bvt[idx];
        float y = 1.f / (1.f + expf(-x));
        float v = visible[idx + VDIM];  // visible[(t+1)*V + j] == visible[idx + V]
        float term = -(v * logf(1e-6f + y) + (1.f - v) * logf(1e-6f + 1.f - y));
        s += (double)term;
    }
    sd[threadIdx.x] = s;
    __syncthreads();
    for (int o = 128; o; o >>= 1) {
        if (threadIdx.x < o) sd[threadIdx.x] += sd[threadIdx.x + o];
        __syncthreads();
    }
    if (threadIdx.x == 0) out[blockIdx.x] = sd[0];
}

__global__ void sqsum_kernel(const float* __restrict__ x, int n, double* __restrict__ out) {
    __shared__ double sd[256];
    double s = 0.0;
    for (int i = blockIdx.x * 256 + threadIdx.x; i < n; i += gridDim.x * 256) {
        float f = x[i];
        s += (double)f * (double)f;
    }
    sd[threadIdx.x] = s;
    __syncthreads();
    for (int o = 128; o; o >>= 1) {
        if (threadIdx.x < o) sd[threadIdx.x] += sd[threadIdx.x + o];
        __syncthreads();
    }
    if (threadIdx.x == 0) out[blockIdx.x] = sd[0];
}

__global__ void mse_kernel(const float* __restrict__ visible,
                           const float* __restrict__ vneg, float* __restrict__ out) {
    int t = blockIdx.x * blockDim.x + threadIdx.x;
    if (t < NTT) {
        float s = 0.f;
#pragma unroll 8
        for (int j = 0; j < VDIM; j++)
            s += fabsf(visible[(t + 1) * VDIM + j] - vneg[t * VDIM + j]);
        out[1 + t] = s / 88.0f;
    }
}

__global__ void finalize_kernel(const double* __restrict__ ce,
                                const double* __restrict__ n2uv,
                                const double* __restrict__ n2uh,
                                float* __restrict__ out) {
    __shared__ double s[256];
    const int t = threadIdx.x;
    s[t] = ce[t];
    __syncthreads();
    for (int o = 128; o; o >>= 1) { if (t < o) s[t] += s[t + o]; __syncthreads(); }
    double ce_sum = s[0];
    __syncthreads();
    s[t] = (t < 64) ? n2uv[t] : 0.0;
    __syncthreads();
    for (int o = 128; o; o >>= 1) { if (t < o) s[t] += s[t + o]; __syncthreads(); }
    double suv = s[0];
    __syncthreads();
    s[t] = (t < 64) ? n2uh[t] : 0.0;
    __syncthreads();
    for (int o = 128; o; o >>= 1) { if (t < o) s[t] += s[t + o]; __syncthreads(); }
    double suh = s[0];
    if (t == 0) {
        double reg = 0.2 * (sqrt(suv) + sqrt(suh));
        out[0]      = (float)(ce_sum / (double)TSTEPS + reg);
        out[TSTEPS] = (float)reg;   // index 4096
    }
}

// ---------------------------------------------------------------------------
// Launch
// ---------------------------------------------------------------------------
extern "C" void kernel_launch(void* const* d_in, const int* in_sizes, int n_in,
                              void* d_out, int out_size) {
    const float* visible = (const float*)d_in[0];
    const float* rand_h  = (const float*)d_in[1];
    const float* rand_v  = (const float*)d_in[2];
    const float* w       = (const float*)d_in[3];
    const float* wuu     = (const float*)d_in[4];
    const float* wuv     = (const float*)d_in[5];
    const float* wuh     = (const float*)d_in[6];
    const float* wvu     = (const float*)d_in[7];
    const float* bv      = (const float*)d_in[8];
    const float* bh      = (const float*)d_in[9];
    const float* bu      = (const float*)d_in[10];
    const float* u0      = (const float*)d_in[11];
    float* out = (float*)d_out;

    void *pa, *pu, *pbh, *pbv, *ph, *pv, *pwT, *pce, *pnuv, *pnuh;
    cudaGetSymbolAddress(&pa,   g_a);
    cudaGetSymbolAddress(&pu,   g_uprev);
    cudaGetSymbolAddress(&pbh,  g_bht);
    cudaGetSymbolAddress(&pbv,  g_bvt);
    cudaGetSymbolAddress(&ph,   g_h);
    cudaGetSymbolAddress(&pv,   g_v);
    cudaGetSymbolAddress(&pwT,  g_wT);
    cudaGetSymbolAddress(&pce,  g_ce);
    cudaGetSymbolAddress(&pnuv, g_n2uv);
    cudaGetSymbolAddress(&pnuh, g_n2uh);

    // 0) transpose w -> wT (V, H)
    transpose_w_kernel<<<(HDIM * VDIM + 255) / 256, 256>>>(w, (float*)pwT);

    // 1) a[t] = v_seq[t] @ wvu^T + bu   (M=4095, N=512, K=88); v_seq = visible+V
    {
        dim3 g((NTT + 63) / 64, (RDIM + 63) / 64);
        gemm_nt<<<g, 256>>>(visible + VDIM, VDIM, wvu, VDIM,
                            bu, 0, nullptr, 0,
                            (float*)pa, RDIM, NTT, RDIM, VDIM);
    }

    // 2) sequential recurrence -> u_prev
    recur_kernel<<<8, 512>>>(wuu, (const float*)pa, u0, (float*)pu);

    // 3) bh_t = u_prev @ wuh^T + bh ; bv_t = u_prev @ wuv^T + bv
    {
        dim3 g((NTT + 63) / 64, (HDIM + 63) / 64);
        gemm_nt<<<g, 256>>>((const float*)pu, RDIM, wuh, RDIM,
                            bh, 0, nullptr, 0,
                            (float*)pbh, HDIM, NTT, HDIM, RDIM);
        dim3 g2((NTT + 63) / 64, (VDIM + 63) / 64);
        gemm_nt<<<g2, 256>>>((const float*)pu, RDIM, wuv, RDIM,
                             bv, 0, nullptr, 0,
                             (float*)pbv, VDIM, NTT, VDIM, RDIM);
    }

    // 4) Gibbs: v starts as v_seq
    cudaMemcpyAsync(pv, visible + VDIM, (size_t)NTT * VDIM * sizeof(float),
                    cudaMemcpyDeviceToDevice, 0);
    {
        dim3 gh((NTT + 63) / 64, (HDIM + 63) / 64);
        dim3 gv((NTT + 63) / 64, (VDIM + 63) / 64);
        for (int s = 0; s < GS; s++) {
            // h = 1[ sigmoid(v @ w^T + bh_t) > rand_h[:,s,:] ]
            gemm_nt<<<gh, 256>>>((const float*)pv, VDIM, w, VDIM,
                                 (const float*)pbh, HDIM,
                                 rand_h + (size_t)s * HDIM, GS * HDIM,
                                 (float*)ph, HDIM, NTT, HDIM, VDIM);
            // v = 1[ sigmoid(h @ w + bv_t) > rand_v[:,s,:] ]   (B = wT, NT form)
            gemm_nt<<<gv, 256>>>((const float*)ph, HDIM, (const float*)pwT, HDIM,
                                 (const float*)pbv, VDIM,
                                 rand_v + (size_t)s * VDIM, GS * VDIM,
                                 (float*)pv, VDIM, NTT, VDIM, HDIM);
        }
    }

    // 5) reductions
    ce_partial_kernel<<<256, 256>>>(visible, (const float*)pbv, (double*)pce);
    sqsum_kernel<<<64, 256>>>(wuv, VDIM * RDIM, (double*)pnuv);
    sqsum_kernel<<<64, 256>>>(wuh, HDIM * RDIM, (double*)pnuh);
    mse_kernel<<<(NTT + 255) / 256, 256>>>(visible, (const float*)pv, out);
    finalize_kernel<<<1, 256>>>((const double*)pce, (const double*)pnuv,
                                (const double*)pnuh, out);
}

// round 10
// speedup vs baseline: 1.6160x; 1.0278x over previous
#include <cuda_runtime.h>
#include <cstdint>
#include <cstdio>

#define TSTEPS 4096
#define NTT    4095
#define VDIM   88
#define HDIM   512
#define RDIM   512
#define GS     20

typedef unsigned long long ull;

// ---------------------------------------------------------------------------
// Scratch (static device globals — no runtime allocation allowed)
// ---------------------------------------------------------------------------
__device__ float  g_a    [NTT * RDIM];
__device__ float  g_uprev[NTT * RDIM];
__device__ float  g_bht  [NTT * HDIM];
__device__ float  g_bvt  [NTT * VDIM];
__device__ float  g_h    [NTT * HDIM];
__device__ float  g_v    [NTT * VDIM];
__device__ float  g_wT   [VDIM * HDIM];
__device__ double g_ce   [256];
__device__ double g_n2uv [64];
__device__ double g_n2uh [64];

// ---------------------------------------------------------------------------
// Helpers: packed fp32x2 ops (componentwise IEEE fp32 — order-preserving)
// ---------------------------------------------------------------------------
__device__ __forceinline__ ull fma2_(ull a, ull b, ull c) {
    ull d; asm("fma.rn.f32x2 %0, %1, %2, %3;" : "=l"(d) : "l"(a), "l"(b), "l"(c));
    return d;
}
__device__ __forceinline__ ull add2_(ull a, ull b) {
    ull d; asm("add.rn.f32x2 %0, %1, %2;" : "=l"(d) : "l"(a), "l"(b));
    return d;
}
__device__ __forceinline__ ull pack2_(float lo, float hi) {
    ull d; asm("mov.b64 %0, {%1, %2};" : "=l"(d) : "f"(lo), "f"(hi));
    return d;
}
__device__ __forceinline__ ull dup2_(float v) {
    ull d; asm("mov.b64 %0, {%1, %1};" : "=l"(d) : "f"(v));
    return d;
}
__device__ __forceinline__ float lo2_(ull v) { return __uint_as_float((unsigned)v); }
__device__ __forceinline__ float hi2_(ull v) { return __uint_as_float((unsigned)(v >> 32)); }

__device__ __forceinline__ void cluster_sync_() {
    asm volatile("barrier.cluster.arrive.aligned;\n\t"
                 "barrier.cluster.wait.aligned;" ::: "memory");
}
__device__ __forceinline__ uint32_t smem_u32(const void* p) {
    return (uint32_t)__cvta_generic_to_shared(p);
}

// ---------------------------------------------------------------------------
// NT GEMM: C[m][n] = sum_k A[m][k]*B[n][k] + bias[m*bs+n]; optional Bernoulli
// epilogue. Tile (16*TM) x 64, K-chunk 16, 256 threads, TM x 4 per thread.
// FFMA2 pairs adjacent M rows; each output's k-ascending chain is bit-exact
// vs the previous scalar kernel (padding contributes exact 0*x terms, same
// as before).
// ---------------------------------------------------------------------------
template <int TM>
__global__ void __launch_bounds__(256) gemm2_nt(
    const float* __restrict__ A, int lda,
    const float* __restrict__ B, int ldb,
    const float* __restrict__ bias, int bias_stride,
    const float* __restrict__ rnd, int rnd_stride,
    float* __restrict__ C, int ldc,
    int M, int N, int K)
{
    constexpr int BM  = 16 * TM;
    constexpr int KW  = TM;        // floats per thread (A staging, k dir)
    constexpr int TPR = 16 / KW;   // threads per A row

    __shared__ __align__(16) float As[16][BM];
    __shared__ __align__(16) float Bs[16][64];

    const int tid = threadIdx.x;
    const int tx  = tid & 15;
    const int ty  = tid >> 4;
    const int m0  = blockIdx.x * BM;
    const int n0  = blockIdx.y * 64;

    // A staging map
    const int arow  = tid / TPR;
    const int akb   = (tid % TPR) * KW;
    const int am    = m0 + arow;
    const bool amok = (am < M);
    // B staging map
    const int brow  = tid >> 2;
    const int bkb   = (tid & 3) * 4;
    const int bn    = n0 + brow;
    const bool bnok = (bn < N);

    ull acc[TM / 2][4];
#pragma unroll
    for (int i = 0; i < TM / 2; i++)
#pragma unroll
        for (int j = 0; j < 4; j++) acc[i][j] = 0ull;

    for (int k0 = 0; k0 < K; k0 += 16) {
#pragma unroll
        for (int i = 0; i < KW; i++) {
            int k = k0 + akb + i;
            As[akb + i][arow] = (amok && k < K) ? A[(size_t)am * lda + k] : 0.f;
        }
#pragma unroll
        for (int i = 0; i < 4; i++) {
            int k = k0 + bkb + i;
            Bs[bkb + i][brow] = (bnok && k < K) ? B[(size_t)bn * ldb + k] : 0.f;
        }
        __syncthreads();
#pragma unroll
        for (int k = 0; k < 16; k++) {
            float4 b4 = *(const float4*)&Bs[k][tx * 4];
            ull bb[4];
            bb[0] = dup2_(b4.x); bb[1] = dup2_(b4.y);
            bb[2] = dup2_(b4.z); bb[3] = dup2_(b4.w);
#pragma unroll
            for (int q = 0; q < TM / 4; q++) {
                ulonglong2 aa = *(const ulonglong2*)&As[k][ty * TM + q * 4];
#pragma unroll
                for (int c = 0; c < 4; c++) {
                    acc[2 * q + 0][c] = fma2_(aa.x, bb[c], acc[2 * q + 0][c]);
                    acc[2 * q + 1][c] = fma2_(aa.y, bb[c], acc[2 * q + 1][c]);
                }
            }
        }
        __syncthreads();
    }

    // Epilogue: acc[i] lo -> row ty*TM+2i, hi -> row ty*TM+2i+1
#pragma unroll
    for (int i = 0; i < TM / 2; i++) {
#pragma unroll
        for (int half = 0; half < 2; half++) {
            const int m = m0 + ty * TM + 2 * i + half;
            if (m >= M) continue;
#pragma unroll
            for (int c = 0; c < 4; c++) {
                const int n = n0 + tx * 4 + c;
                if (n >= N) continue;
                float v = half ? hi2_(acc[i][c]) : lo2_(acc[i][c]);
                float val = v + bias[(size_t)m * bias_stride + n];
                if (rnd) {
                    float s = 1.f / (1.f + expf(-val));
                    val = (s > rnd[(size_t)m * rnd_stride + n]) ? 1.f : 0.f;
                }
                C[(size_t)m * ldc + n] = val;
            }
        }
    }
}

// ---------------------------------------------------------------------------
// Sequential u recurrence: cluster of 8 CTAs, wuu register-resident.
// Packed FFMA2 dot (outputs o0/o1 and o2/o3 paired) + packed 64-bit butterfly.
// Per-component accumulation order identical to the scalar version.
// ---------------------------------------------------------------------------
__global__ void __cluster_dims__(8, 1, 1) __launch_bounds__(512, 1)
recur_kernel(const float* __restrict__ wuu, const float* __restrict__ a,
             const float* __restrict__ u0, float* __restrict__ uprev)
{
    __shared__ float u_s[2][RDIM];

    unsigned rank;
    asm("mov.u32 %0, %%cluster_ctarank;" : "=r"(rank));

    const int tid = threadIdx.x;
    const int w = tid >> 5, l = tid & 31;
    const int obase = (int)rank * 64 + w * 4;

    // Packed weights: w01[j] = (wuu[o0][l+32j], wuu[o1][l+32j]), w23 likewise.
    ull w01[16], w23[16];
#pragma unroll
    for (int j = 0; j < 16; j++) {
        w01[j] = pack2_(wuu[(obase + 0) * RDIM + l + 32 * j],
                        wuu[(obase + 1) * RDIM + l + 32 * j]);
        w23[j] = pack2_(wuu[(obase + 2) * RDIM + l + 32 * j],
                        wuu[(obase + 3) * RDIM + l + 32 * j]);
    }

    u_s[0][tid] = u0[tid];
    if (rank == 0) uprev[tid] = u0[tid];

    const uint32_t base0 = smem_u32(&u_s[0][0]);
    const uint32_t base1 = smem_u32(&u_s[1][0]);

    cluster_sync_();

    int p = 0;
    for (int t = 0; t < NTT - 1; t++) {
        float av = 0.f;
        if (l < 4) av = a[t * RDIM + obase + l];

        const float* us = u_s[p];
        ull s01 = 0ull, s23 = 0ull;
#pragma unroll
        for (int j = 0; j < 16; j++) {
            ull up = dup2_(us[l + 32 * j]);
            s01 = fma2_(w01[j], up, s01);
            s23 = fma2_(w23[j], up, s23);
        }
#pragma unroll
        for (int off = 16; off; off >>= 1) {
            s01 = add2_(s01, __shfl_xor_sync(0xffffffffu, s01, off));
            s23 = add2_(s23, __shfl_xor_sync(0xffffffffu, s23, off));
        }
        if (l < 4) {
            float acc = (l == 0) ? lo2_(s01) : (l == 1) ? hi2_(s01)
                      : (l == 2) ? lo2_(s23) : hi2_(s23);
            float un = tanhf(acc + av);
            uint32_t dst = (p ? base0 : base1) + 4u * (uint32_t)(obase + l);
#pragma unroll
            for (unsigned r = 0; r < 8; r++) {
                uint32_t rem;
                asm volatile("mapa.shared::cluster.u32 %0, %1, %2;"
                             : "=r"(rem) : "r"(dst), "r"(r));
                asm volatile("st.shared::cluster.f32 [%0], %1;"
                             :: "r"(rem), "f"(un) : "memory");
            }
            uprev[(t + 1) * RDIM + obase + l] = un;
        }
        cluster_sync_();
        p ^= 1;
    }
}

// ---------------------------------------------------------------------------
// Small utility kernels (unchanged)
// ---------------------------------------------------------------------------
__global__ void transpose_w_kernel(const float* __restrict__ w, float* __restrict__ wT) {
    int idx = blockIdx.x * blockDim.x + threadIdx.x;
    if (idx < HDIM * VDIM) {
        int i = idx / VDIM, j = idx % VDIM;
        wT[j * HDIM + i] = w[idx];
    }
}

__global__ void ce_partial_kernel(const float* __restrict__ visible,
                                  const float* __restrict__ bvt, double* __restrict__ out) {
    __shared__ double sd[256];
    double s = 0.0;
    const int n = NTT * VDIM;
    for (int idx = blockIdx.x * 256 + threadIdx.x; idx < n; idx += gridDim.x * 256) {
        float x = bvt[idx];
        float y = 1.f / (1.f + expf(-x));
        float v = visible[idx + VDIM];
        float term = -(v * logf(1e-6f + y) + (1.f - v) * logf(1e-6f + 1.f - y));
        s += (double)term;
    }
    sd[threadIdx.x] = s;
    __syncthreads();
    for (int o = 128; o; o >>= 1) {
        if (threadIdx.x < o) sd[threadIdx.x] += sd[threadIdx.x + o];
        __syncthreads();
    }
    if (threadIdx.x == 0) out[blockIdx.x] = sd[0];
}

__global__ void sqsum_kernel(const float* __restrict__ x, int n, double* __restrict__ out) {
    __shared__ double sd[256];
    double s = 0.0;
    for (int i = blockIdx.x * 256 + threadIdx.x; i < n; i += gridDim.x * 256) {
        float f = x[i];
        s += (double)f * (double)f;
    }
    sd[threadIdx.x] = s;
    __syncthreads();
    for (int o = 128; o; o >>= 1) {
        if (threadIdx.x < o) sd[threadIdx.x] += sd[threadIdx.x + o];
        __syncthreads();
    }
    if (threadIdx.x == 0) out[blockIdx.x] = sd[0];
}

__global__ void mse_kernel(const float* __restrict__ visible,
                           const float* __restrict__ vneg, float* __restrict__ out) {
    int t = blockIdx.x * blockDim.x + threadIdx.x;
    if (t < NTT) {
        float s = 0.f;
#pragma unroll 8
        for (int j = 0; j < VDIM; j++)
            s += fabsf(visible[(t + 1) * VDIM + j] - vneg[t * VDIM + j]);
        out[1 + t] = s / 88.0f;
    }
}

__global__ void finalize_kernel(const double* __restrict__ ce,
                                const double* __restrict__ n2uv,
                                const double* __restrict__ n2uh,
                                float* __restrict__ out) {
    __shared__ double s[256];
    const int t = threadIdx.x;
    s[t] = ce[t];
    __syncthreads();
    for (int o = 128; o; o >>= 1) { if (t < o) s[t] += s[t + o]; __syncthreads(); }
    double ce_sum = s[0];
    __syncthreads();
    s[t] = (t < 64) ? n2uv[t] : 0.0;
    __syncthreads();
    for (int o = 128; o; o >>= 1) { if (t < o) s[t] += s[t + o]; __syncthreads(); }
    double suv = s[0];
    __syncthreads();
    s[t] = (t < 64) ? n2uh[t] : 0.0;
    __syncthreads();
    for (int o = 128; o; o >>= 1) { if (t < o) s[t] += s[t + o]; __syncthreads(); }
    double suh = s[0];
    if (t == 0) {
        double reg = 0.2 * (sqrt(suv) + sqrt(suh));
        out[0]      = (float)(ce_sum / (double)TSTEPS + reg);
        out[TSTEPS] = (float)reg;
    }
}

// ---------------------------------------------------------------------------
// Launch
// ---------------------------------------------------------------------------
extern "C" void kernel_launch(void* const* d_in, const int* in_sizes, int n_in,
                              void* d_out, int out_size) {
    const float* visible = (const float*)d_in[0];
    const float* rand_h  = (const float*)d_in[1];
    const float* rand_v  = (const float*)d_in[2];
    const float* w       = (const float*)d_in[3];
    const float* wuu     = (const float*)d_in[4];
    const float* wuv     = (const float*)d_in[5];
    const float* wuh     = (const float*)d_in[6];
    const float* wvu     = (const float*)d_in[7];
    const float* bv      = (const float*)d_in[8];
    const float* bh      = (const float*)d_in[9];
    const float* bu      = (const float*)d_in[10];
    const float* u0      = (const float*)d_in[11];
    float* out = (float*)d_out;

    void *pa, *pu, *pbh, *pbv, *ph, *pv, *pwT, *pce, *pnuv, *pnuh;
    cudaGetSymbolAddress(&pa,   g_a);
    cudaGetSymbolAddress(&pu,   g_uprev);
    cudaGetSymbolAddress(&pbh,  g_bht);
    cudaGetSymbolAddress(&pbv,  g_bvt);
    cudaGetSymbolAddress(&ph,   g_h);
    cudaGetSymbolAddress(&pv,   g_v);
    cudaGetSymbolAddress(&pwT,  g_wT);
    cudaGetSymbolAddress(&pce,  g_ce);
    cudaGetSymbolAddress(&pnuv, g_n2uv);
    cudaGetSymbolAddress(&pnuh, g_n2uh);

    // 0) transpose w -> wT (V, H)
    transpose_w_kernel<<<(HDIM * VDIM + 255) / 256, 256>>>(w, (float*)pwT);

    // 1) a[t] = v_seq[t] @ wvu^T + bu   (M=4095, N=512, K=88)
    {
        dim3 g((NTT + 127) / 128, (RDIM + 63) / 64);
        gemm2_nt<8><<<g, 256>>>(visible + VDIM, VDIM, wvu, VDIM,
                                bu, 0, nullptr, 0,
                                (float*)pa, RDIM, NTT, RDIM, VDIM);
    }

    // 2) sequential recurrence -> u_prev
    recur_kernel<<<8, 512>>>(wuu, (const float*)pa, u0, (float*)pu);

    // 3) bh_t = u_prev @ wuh^T + bh ; bv_t = u_prev @ wuv^T + bv
    {
        dim3 g((NTT + 127) / 128, (HDIM + 63) / 64);
        gemm2_nt<8><<<g, 256>>>((const float*)pu, RDIM, wuh, RDIM,
                                bh, 0, nullptr, 0,
                                (float*)pbh, HDIM, NTT, HDIM, RDIM);
        dim3 g2((NTT + 63) / 64, (VDIM + 63) / 64);
        gemm2_nt<4><<<g2, 256>>>((const float*)pu, RDIM, wuv, RDIM,
                                 bv, 0, nullptr, 0,
                                 (float*)pbv, VDIM, NTT, VDIM, RDIM);
    }

    // 4) Gibbs: v starts as v_seq
    cudaMemcpyAsync(pv, visible + VDIM, (size_t)NTT * VDIM * sizeof(float),
                    cudaMemcpyDeviceToDevice, 0);
    {
        dim3 gh((NTT + 127) / 128, (HDIM + 63) / 64);
        dim3 gv((NTT + 63) / 64, (VDIM + 63) / 64);
        for (int s = 0; s < GS; s++) {
            gemm2_nt<8><<<gh, 256>>>((const float*)pv, VDIM, w, VDIM,
                                     (const float*)pbh, HDIM,
                                     rand_h + (size_t)s * HDIM, GS * HDIM,
                                     (float*)ph, HDIM, NTT, HDIM, VDIM);
            gemm2_nt<4><<<gv, 256>>>((const float*)ph, HDIM, (const float*)pwT, HDIM,
                                     (const float*)pbv, VDIM,
                                     rand_v + (size_t)s * VDIM, GS * VDIM,
                                     (float*)pv, VDIM, NTT, VDIM, HDIM);
        }
    }

    // 5) reductions
    ce_partial_kernel<<<256, 256>>>(visible, (const float*)pbv, (double*)pce);
    sqsum_kernel<<<64, 256>>>(wuv, VDIM * RDIM, (double*)pnuv);
    sqsum_kernel<<<64, 256>>>(wuh, HDIM * RDIM, (double*)pnuh);
    mse_kernel<<<(NTT + 255) / 256, 256>>>(visible, (const float*)pv, out);
    finalize_kernel<<<1, 256>>>((const double*)pce, (const double*)pnuv,
                                (const double*)pnuh, out);
}